// round 1
// baseline (speedup 1.0000x reference)
#include <cuda_runtime.h>
#include <cuda_bf16.h>
#include <math.h>

// ---------------------------------------------------------------------------
// Swin Transformer block, fp32 baseline.
// B=16, H=W=56, C=192, WS=7, SHIFT=3, NH=6, hd=32.
// Tokens T = 16*56*56 = 50176 = 1024 windows * 49.
// ---------------------------------------------------------------------------

#define T_TOKENS 50176
#define C_DIM    192
#define NWIN     1024
#define NTOK     49
#define NH_      6
#define HD_      32
#define WS_      7
#define SHIFT_   3
#define HW_      56

// Scratch (device globals: allocation-free rule)
__device__ float g_xw  [T_TOKENS * C_DIM];   // LN1+shift+window-partitioned; reused for attn out
__device__ float g_qkv [T_TOKENS * 3 * C_DIM];
__device__ float g_y   [T_TOKENS * C_DIM];   // proj output (window layout)
__device__ float g_x2  [T_TOKENS * C_DIM];   // shortcut + attn branch
__device__ float g_h2  [T_TOKENS * C_DIM];   // LN2 output
__device__ float g_mlp [T_TOKENS * 4 * C_DIM];

// ---------------------------------------------------------------------------
// Block LayerNorm stats (blockDim.x == 192)
// ---------------------------------------------------------------------------
__device__ __forceinline__ void block_ln_stats(float v, float& mean, float& rstd) {
    float s = v, s2 = v * v;
    #pragma unroll
    for (int o = 16; o > 0; o >>= 1) {
        s  += __shfl_down_sync(0xffffffffu, s,  o);
        s2 += __shfl_down_sync(0xffffffffu, s2, o);
    }
    __shared__ float ws[6], ws2[6], sm[2];
    int wid = threadIdx.x >> 5, lane = threadIdx.x & 31;
    if (lane == 0) { ws[wid] = s; ws2[wid] = s2; }
    __syncthreads();
    if (threadIdx.x == 0) {
        float t = 0.f, t2 = 0.f;
        #pragma unroll
        for (int i = 0; i < 6; i++) { t += ws[i]; t2 += ws2[i]; }
        float m   = t  * (1.0f / 192.0f);
        float var = t2 * (1.0f / 192.0f) - m * m;
        sm[0] = m;
        sm[1] = rsqrtf(var + 1e-5f);
    }
    __syncthreads();
    mean = sm[0];
    rstd = sm[1];
}

// ---------------------------------------------------------------------------
// K1: LN1 + shift + window partition. One block per window-layout row.
// ---------------------------------------------------------------------------
__global__ void ln1_shift_window_kernel(const float* __restrict__ x,
                                        const float* __restrict__ g,
                                        const float* __restrict__ b,
                                        float* __restrict__ out) {
    int r = blockIdx.x;                // r = w*49 + n
    int w = r / NTOK, n = r % NTOK;
    int bb = w >> 6;                   // /64
    int wr = (w & 63) >> 3;
    int wc = w & 7;
    int wi = n / WS_, wj = n % WS_;
    int si = wr * WS_ + wi, sj = wc * WS_ + wj;
    int i = (si + SHIFT_) % HW_;
    int j = (sj + SHIFT_) % HW_;
    int c = threadIdx.x;
    size_t src = ((size_t)(bb * HW_ + i) * HW_ + j) * C_DIM + c;
    float v = x[src];
    float mean, rstd;
    block_ln_stats(v, mean, rstd);
    out[(size_t)r * C_DIM + c] = (v - mean) * rstd * g[c] + b[c];
}

// ---------------------------------------------------------------------------
// K5: window-reverse scatter + residual + LN2. One block per spatial token.
// ---------------------------------------------------------------------------
__global__ void scatter_res_ln2_kernel(const float* __restrict__ x,
                                       const float* __restrict__ y_win,
                                       const float* __restrict__ g,
                                       const float* __restrict__ b,
                                       float* __restrict__ x2,
                                       float* __restrict__ h2) {
    int t = blockIdx.x;                // t = (b*56 + i)*56 + j
    int j = t % HW_;
    int i = (t / HW_) % HW_;
    int bb = t / (HW_ * HW_);
    int si = (i + HW_ - SHIFT_) % HW_;
    int sj = (j + HW_ - SHIFT_) % HW_;
    int wr = si / WS_, wi = si % WS_;
    int wc = sj / WS_, wj = sj % WS_;
    int w  = bb * 64 + wr * 8 + wc;
    int n  = wi * WS_ + wj;
    int c = threadIdx.x;
    float xv = x[(size_t)t * C_DIM + c];
    float yv = y_win[((size_t)w * NTOK + n) * C_DIM + c];
    float v  = xv + yv;
    x2[(size_t)t * C_DIM + c] = v;
    float mean, rstd;
    block_ln_stats(v, mean, rstd);
    h2[(size_t)t * C_DIM + c] = (v - mean) * rstd * g[c] + b[c];
}

// ---------------------------------------------------------------------------
// Tiled SGEMM: C[M,N] = A[M,K] @ B[K,N] + bias, with epilogue.
// EPI: 0 = bias, 1 = bias+GELU(exact), 2 = bias+residual add.
// BM=128 BN=64 BK=16, 256 threads, 8x4 microtile. All dims divide tiles.
// ---------------------------------------------------------------------------
template <int EPI>
__global__ __launch_bounds__(256, 2)
void gemm_kernel(const float* __restrict__ A, const float* __restrict__ B,
                 const float* __restrict__ bias, const float* __restrict__ res,
                 float* __restrict__ C, int M, int Ncol, int K) {
    constexpr int BM = 128, BN = 64, BK = 16, TM = 8, TN = 4;
    __shared__ float As[BK][BM];
    __shared__ float Bs[BK][BN];
    int tid = threadIdx.x;
    int bm = blockIdx.y * BM;
    int bn = blockIdx.x * BN;
    int tx = tid & 15;     // n-dir (16)
    int ty = tid >> 4;     // m-dir (16)
    float acc[TM][TN];
    #pragma unroll
    for (int i = 0; i < TM; i++)
        #pragma unroll
        for (int jj = 0; jj < TN; jj++) acc[i][jj] = 0.f;

    for (int k0 = 0; k0 < K; k0 += BK) {
        // Load A tile: 128x16 = 512 float4 slots, 2 per thread
        #pragma unroll
        for (int l = 0; l < 2; l++) {
            int s  = tid + l * 256;
            int m  = s >> 2;
            int kq = s & 3;
            float4 a = *(const float4*)(A + (size_t)(bm + m) * K + k0 + kq * 4);
            As[kq * 4 + 0][m] = a.x;
            As[kq * 4 + 1][m] = a.y;
            As[kq * 4 + 2][m] = a.z;
            As[kq * 4 + 3][m] = a.w;
        }
        // Load B tile: 16x64 = 256 float4 slots, 1 per thread
        {
            int k  = tid >> 4;
            int nq = tid & 15;
            *(float4*)(&Bs[k][nq * 4]) =
                *(const float4*)(B + (size_t)(k0 + k) * Ncol + bn + nq * 4);
        }
        __syncthreads();
        #pragma unroll
        for (int k = 0; k < BK; k++) {
            float4 b4 = *(const float4*)(&Bs[k][tx * TN]);
            float ra[TM];
            #pragma unroll
            for (int i = 0; i < TM; i++) ra[i] = As[k][ty * TM + i];
            #pragma unroll
            for (int i = 0; i < TM; i++) {
                acc[i][0] += ra[i] * b4.x;
                acc[i][1] += ra[i] * b4.y;
                acc[i][2] += ra[i] * b4.z;
                acc[i][3] += ra[i] * b4.w;
            }
        }
        __syncthreads();
    }

    int col = bn + tx * TN;
    float4 bv = *(const float4*)(bias + col);
    #pragma unroll
    for (int i = 0; i < TM; i++) {
        int row = bm + ty * TM + i;
        float4 o;
        o.x = acc[i][0] + bv.x;
        o.y = acc[i][1] + bv.y;
        o.z = acc[i][2] + bv.z;
        o.w = acc[i][3] + bv.w;
        if (EPI == 1) {
            o.x = 0.5f * o.x * (1.0f + erff(o.x * 0.70710678118654752f));
            o.y = 0.5f * o.y * (1.0f + erff(o.y * 0.70710678118654752f));
            o.z = 0.5f * o.z * (1.0f + erff(o.z * 0.70710678118654752f));
            o.w = 0.5f * o.w * (1.0f + erff(o.w * 0.70710678118654752f));
        }
        if (EPI == 2) {
            float4 r4 = *(const float4*)(res + (size_t)row * Ncol + col);
            o.x += r4.x; o.y += r4.y; o.z += r4.z; o.w += r4.w;
        }
        *(float4*)(C + (size_t)row * Ncol + col) = o;
    }
}

// ---------------------------------------------------------------------------
// K3: fused window attention, one block per (window, head).
// scores + relative-position bias + softmax + PV, all in shared memory.
// ---------------------------------------------------------------------------
__global__ __launch_bounds__(256)
void attn_kernel(const float* __restrict__ qkv,
                 const float* __restrict__ bias_table,
                 float* __restrict__ out) {
    int w = blockIdx.x;
    int h = blockIdx.y;
    __shared__ float qs[NTOK][HD_ + 1];
    __shared__ float ks[NTOK][HD_ + 1];
    __shared__ float vs[NTOK][HD_ + 1];
    __shared__ float sc[NTOK][NTOK + 1];
    int tid = threadIdx.x;
    const float scale = 0.17677669529663687f;   // 32^-0.5

    for (int i = tid; i < NTOK * HD_; i += 256) {
        int n = i >> 5, d = i & 31;
        size_t base = ((size_t)(w * NTOK + n)) * (3 * C_DIM) + h * HD_ + d;
        qs[n][d] = qkv[base] * scale;
        ks[n][d] = qkv[base + C_DIM];
        vs[n][d] = qkv[base + 2 * C_DIM];
    }
    __syncthreads();

    for (int i = tid; i < NTOK * NTOK; i += 256) {
        int n = i / NTOK, m = i % NTOK;
        float a = 0.f;
        #pragma unroll
        for (int d = 0; d < HD_; d++) a += qs[n][d] * ks[m][d];
        int ni = n / WS_, nj = n % WS_;
        int mi = m / WS_, mj = m % WS_;
        int ridx = (ni - mi + WS_ - 1) * (2 * WS_ - 1) + (nj - mj + WS_ - 1);
        sc[n][m] = a + bias_table[ridx * NH_ + h];
    }
    __syncthreads();

    if (tid < NTOK) {
        float mx = -1e30f;
        #pragma unroll 7
        for (int m = 0; m < NTOK; m++) mx = fmaxf(mx, sc[tid][m]);
        float sum = 0.f;
        #pragma unroll 7
        for (int m = 0; m < NTOK; m++) {
            float e = __expf(sc[tid][m] - mx);
            sc[tid][m] = e;
            sum += e;
        }
        float inv = 1.0f / sum;
        #pragma unroll 7
        for (int m = 0; m < NTOK; m++) sc[tid][m] *= inv;
    }
    __syncthreads();

    for (int i = tid; i < NTOK * HD_; i += 256) {
        int n = i >> 5, d = i & 31;
        float a = 0.f;
        #pragma unroll 7
        for (int m = 0; m < NTOK; m++) a += sc[n][m] * vs[m][d];
        out[((size_t)(w * NTOK + n)) * C_DIM + h * HD_ + d] = a;
    }
}

// ---------------------------------------------------------------------------
// Launch
// ---------------------------------------------------------------------------
extern "C" void kernel_launch(void* const* d_in, const int* in_sizes, int n_in,
                              void* d_out, int out_size) {
    const float* x          = (const float*)d_in[0];
    const float* qkv_w      = (const float*)d_in[1];
    const float* qkv_b      = (const float*)d_in[2];
    const float* proj_w     = (const float*)d_in[3];
    const float* proj_b     = (const float*)d_in[4];
    const float* bias_table = (const float*)d_in[5];
    const float* norm1_g    = (const float*)d_in[6];
    const float* norm1_b    = (const float*)d_in[7];
    const float* norm2_g    = (const float*)d_in[8];
    const float* norm2_b    = (const float*)d_in[9];
    const float* mlp_w1     = (const float*)d_in[10];
    const float* mlp_b1     = (const float*)d_in[11];
    const float* mlp_w2     = (const float*)d_in[12];
    const float* mlp_b2     = (const float*)d_in[13];
    float* out = (float*)d_out;

    float *p_xw, *p_qkv, *p_y, *p_x2, *p_h2, *p_mlp;
    cudaGetSymbolAddress((void**)&p_xw,  g_xw);
    cudaGetSymbolAddress((void**)&p_qkv, g_qkv);
    cudaGetSymbolAddress((void**)&p_y,   g_y);
    cudaGetSymbolAddress((void**)&p_x2,  g_x2);
    cudaGetSymbolAddress((void**)&p_h2,  g_h2);
    cudaGetSymbolAddress((void**)&p_mlp, g_mlp);

    // K1: LN1 + shift + window partition
    ln1_shift_window_kernel<<<T_TOKENS, C_DIM>>>(x, norm1_g, norm1_b, p_xw);

    // K2: QKV GEMM  [50176,192] @ [192,576]
    {
        dim3 grid(576 / 64, T_TOKENS / 128);
        gemm_kernel<0><<<grid, 256>>>(p_xw, qkv_w, qkv_b, nullptr, p_qkv,
                                      T_TOKENS, 3 * C_DIM, C_DIM);
    }

    // K3: fused window attention -> overwrites g_xw (window layout)
    {
        dim3 grid(NWIN, NH_);
        attn_kernel<<<grid, 256>>>(p_qkv, bias_table, p_xw);
    }

    // K4: proj GEMM  [50176,192] @ [192,192]
    {
        dim3 grid(192 / 64, T_TOKENS / 128);
        gemm_kernel<0><<<grid, 256>>>(p_xw, proj_w, proj_b, nullptr, p_y,
                                      T_TOKENS, C_DIM, C_DIM);
    }

    // K5: window reverse scatter + residual + LN2
    scatter_res_ln2_kernel<<<T_TOKENS, C_DIM>>>(x, p_y, norm2_g, norm2_b,
                                                p_x2, p_h2);

    // K6: MLP1 GEMM + GELU  [50176,192] @ [192,768]
    {
        dim3 grid(768 / 64, T_TOKENS / 128);
        gemm_kernel<1><<<grid, 256>>>(p_h2, mlp_w1, mlp_b1, nullptr, p_mlp,
                                      T_TOKENS, 4 * C_DIM, C_DIM);
    }

    // K7: MLP2 GEMM + residual  [50176,768] @ [768,192] -> d_out
    {
        dim3 grid(192 / 64, T_TOKENS / 128);
        gemm_kernel<2><<<grid, 256>>>(p_mlp, mlp_w2, mlp_b2, p_x2, out,
                                      T_TOKENS, C_DIM, 4 * C_DIM);
    }
}

// round 9
// speedup vs baseline: 1.6719x; 1.6719x over previous
#include <cuda_runtime.h>
#include <cuda_bf16.h>
#include <math.h>
#include <stdint.h>

// ---------------------------------------------------------------------------
// Swin Transformer block. GEMMs on tensor cores via mma.sync tf32.
// B=16, H=W=56, C=192, WS=7, SHIFT=3, NH=6, hd=32. T = 50176 tokens.
// ---------------------------------------------------------------------------

#define T_TOKENS 50176
#define C_DIM    192
#define NWIN     1024
#define NTOK     49
#define NH_      6
#define HD_      32
#define WS_      7
#define SHIFT_   3
#define HW_      56

__device__ float g_xw  [T_TOKENS * C_DIM];
__device__ float g_qkv [T_TOKENS * 3 * C_DIM];
__device__ float g_y   [T_TOKENS * C_DIM];
__device__ float g_x2  [T_TOKENS * C_DIM];
__device__ float g_h2  [T_TOKENS * C_DIM];
__device__ float g_mlp [T_TOKENS * 4 * C_DIM];

// ---------------------------------------------------------------------------
__device__ __forceinline__ void block_ln_stats(float v, float& mean, float& rstd) {
    float s = v, s2 = v * v;
    #pragma unroll
    for (int o = 16; o > 0; o >>= 1) {
        s  += __shfl_down_sync(0xffffffffu, s,  o);
        s2 += __shfl_down_sync(0xffffffffu, s2, o);
    }
    __shared__ float ws[6], ws2[6], sm[2];
    int wid = threadIdx.x >> 5, lane = threadIdx.x & 31;
    if (lane == 0) { ws[wid] = s; ws2[wid] = s2; }
    __syncthreads();
    if (threadIdx.x == 0) {
        float t = 0.f, t2 = 0.f;
        #pragma unroll
        for (int i = 0; i < 6; i++) { t += ws[i]; t2 += ws2[i]; }
        float m   = t  * (1.0f / 192.0f);
        float var = t2 * (1.0f / 192.0f) - m * m;
        sm[0] = m;
        sm[1] = rsqrtf(var + 1e-5f);
    }
    __syncthreads();
    mean = sm[0];
    rstd = sm[1];
}

__global__ void ln1_shift_window_kernel(const float* __restrict__ x,
                                        const float* __restrict__ g,
                                        const float* __restrict__ b,
                                        float* __restrict__ out) {
    int r = blockIdx.x;
    int w = r / NTOK, n = r % NTOK;
    int bb = w >> 6;
    int wr = (w & 63) >> 3;
    int wc = w & 7;
    int wi = n / WS_, wj = n % WS_;
    int si = wr * WS_ + wi, sj = wc * WS_ + wj;
    int i = (si + SHIFT_) % HW_;
    int j = (sj + SHIFT_) % HW_;
    int c = threadIdx.x;
    size_t src = ((size_t)(bb * HW_ + i) * HW_ + j) * C_DIM + c;
    float v = x[src];
    float mean, rstd;
    block_ln_stats(v, mean, rstd);
    out[(size_t)r * C_DIM + c] = (v - mean) * rstd * g[c] + b[c];
}

__global__ void scatter_res_ln2_kernel(const float* __restrict__ x,
                                       const float* __restrict__ y_win,
                                       const float* __restrict__ g,
                                       const float* __restrict__ b,
                                       float* __restrict__ x2,
                                       float* __restrict__ h2) {
    int t = blockIdx.x;
    int j = t % HW_;
    int i = (t / HW_) % HW_;
    int bb = t / (HW_ * HW_);
    int si = (i + HW_ - SHIFT_) % HW_;
    int sj = (j + HW_ - SHIFT_) % HW_;
    int wr = si / WS_, wi = si % WS_;
    int wc = sj / WS_, wj = sj % WS_;
    int w  = bb * 64 + wr * 8 + wc;
    int n  = wi * WS_ + wj;
    int c = threadIdx.x;
    float xv = x[(size_t)t * C_DIM + c];
    float yv = y_win[((size_t)w * NTOK + n) * C_DIM + c];
    float v  = xv + yv;
    x2[(size_t)t * C_DIM + c] = v;
    float mean, rstd;
    block_ln_stats(v, mean, rstd);
    h2[(size_t)t * C_DIM + c] = (v - mean) * rstd * g[c] + b[c];
}

// ---------------------------------------------------------------------------
// TF32 tensor-core GEMM: C[M,N] = A[M,K] @ B[K,N] + bias (+epilogue)
// BM=128 BN=64 BK=32, 256 thr (8 warps as 4m x 2n), warp tile 32x32.
// EPI: 0=bias, 1=bias+GELU(exact), 2=bias+residual
// ---------------------------------------------------------------------------
__device__ __forceinline__ uint32_t f2tf(float x) {
    uint32_t r;
    asm("cvt.rna.tf32.f32 %0, %1;" : "=r"(r) : "f"(x));
    return r;
}

__device__ __forceinline__ void mma_tf32(float* c, const uint32_t* a, const uint32_t* b) {
    asm volatile(
        "mma.sync.aligned.m16n8k8.row.col.f32.tf32.tf32.f32 "
        "{%0,%1,%2,%3}, {%4,%5,%6,%7}, {%8,%9}, {%0,%1,%2,%3};"
        : "+f"(c[0]), "+f"(c[1]), "+f"(c[2]), "+f"(c[3])
        : "r"(a[0]), "r"(a[1]), "r"(a[2]), "r"(a[3]), "r"(b[0]), "r"(b[1]));
}

template <int EPI>
__global__ __launch_bounds__(256, 2)
void gemm_tc_kernel(const float* __restrict__ A, const float* __restrict__ B,
                    const float* __restrict__ bias, const float* __restrict__ res,
                    float* __restrict__ C, int M, int Ncol, int K) {
    constexpr int BM = 128, BN = 64, BK = 32;
    constexpr int AST = BK + 4;   // 36: conflict-free fragment LDS
    constexpr int BST = BN + 4;   // 68: conflict-free fragment LDS
    __shared__ float As[BM][AST];
    __shared__ float Bs[BK][BST];

    int tid  = threadIdx.x;
    int wid  = tid >> 5;
    int lane = tid & 31;
    int grp  = lane >> 2;
    int qid  = lane & 3;
    int wm   = wid & 3;
    int wn   = wid >> 2;
    int bm = blockIdx.y * BM;
    int bn = blockIdx.x * BN;

    float acc[2][4][4];
    #pragma unroll
    for (int mi = 0; mi < 2; mi++)
        #pragma unroll
        for (int ni = 0; ni < 4; ni++)
            #pragma unroll
            for (int e = 0; e < 4; e++) acc[mi][ni][e] = 0.f;

    int am[4], akq[4];
    #pragma unroll
    for (int i = 0; i < 4; i++) {
        int f = tid + i * 256;
        am[i] = f >> 3;
        akq[i] = f & 7;
    }
    int bk[2], bnq[2];
    #pragma unroll
    for (int i = 0; i < 2; i++) {
        int f = tid + i * 256;
        bk[i] = f >> 4;
        bnq[i] = f & 15;
    }

    float4 ra[4], rb[2];
    #pragma unroll
    for (int i = 0; i < 4; i++)
        ra[i] = *(const float4*)(A + (size_t)(bm + am[i]) * K + akq[i] * 4);
    #pragma unroll
    for (int i = 0; i < 2; i++)
        rb[i] = *(const float4*)(B + (size_t)bk[i] * Ncol + bn + bnq[i] * 4);

    int iters = K / BK;
    for (int it = 0; it < iters; it++) {
        #pragma unroll
        for (int i = 0; i < 4; i++) {
            float* p = &As[am[i]][akq[i] * 4];
            p[0] = __uint_as_float(f2tf(ra[i].x));
            p[1] = __uint_as_float(f2tf(ra[i].y));
            p[2] = __uint_as_float(f2tf(ra[i].z));
            p[3] = __uint_as_float(f2tf(ra[i].w));
        }
        #pragma unroll
        for (int i = 0; i < 2; i++) {
            float* p = &Bs[bk[i]][bnq[i] * 4];
            p[0] = __uint_as_float(f2tf(rb[i].x));
            p[1] = __uint_as_float(f2tf(rb[i].y));
            p[2] = __uint_as_float(f2tf(rb[i].z));
            p[3] = __uint_as_float(f2tf(rb[i].w));
        }
        __syncthreads();

        if (it + 1 < iters) {
            int k0 = (it + 1) * BK;
            #pragma unroll
            for (int i = 0; i < 4; i++)
                ra[i] = *(const float4*)(A + (size_t)(bm + am[i]) * K + k0 + akq[i] * 4);
            #pragma unroll
            for (int i = 0; i < 2; i++)
                rb[i] = *(const float4*)(B + (size_t)(k0 + bk[i]) * Ncol + bn + bnq[i] * 4);
        }

        #pragma unroll
        for (int ks = 0; ks < 4; ks++) {
            int kk = ks * 8;
            uint32_t af[2][4];
            #pragma unroll
            for (int mi = 0; mi < 2; mi++) {
                int r = wm * 32 + mi * 16 + grp;
                af[mi][0] = __float_as_uint(As[r][kk + qid]);
                af[mi][1] = __float_as_uint(As[r + 8][kk + qid]);
                af[mi][2] = __float_as_uint(As[r][kk + qid + 4]);
                af[mi][3] = __float_as_uint(As[r + 8][kk + qid + 4]);
            }
            uint32_t bf[4][2];
            #pragma unroll
            for (int ni = 0; ni < 4; ni++) {
                int c = wn * 32 + ni * 8 + grp;
                bf[ni][0] = __float_as_uint(Bs[kk + qid][c]);
                bf[ni][1] = __float_as_uint(Bs[kk + qid + 4][c]);
            }
            #pragma unroll
            for (int mi = 0; mi < 2; mi++)
                #pragma unroll
                for (int ni = 0; ni < 4; ni++)
                    mma_tf32(acc[mi][ni], af[mi], bf[ni]);
        }
        __syncthreads();
    }

    #pragma unroll
    for (int mi = 0; mi < 2; mi++) {
        #pragma unroll
        for (int ni = 0; ni < 4; ni++) {
            int col = bn + wn * 32 + ni * 8 + qid * 2;
            float2 bv = *(const float2*)(bias + col);
            #pragma unroll
            for (int half = 0; half < 2; half++) {
                int row = bm + wm * 32 + mi * 16 + grp + half * 8;
                float2 o;
                o.x = acc[mi][ni][half * 2 + 0] + bv.x;
                o.y = acc[mi][ni][half * 2 + 1] + bv.y;
                if (EPI == 1) {
                    o.x = 0.5f * o.x * (1.0f + erff(o.x * 0.70710678118654752f));
                    o.y = 0.5f * o.y * (1.0f + erff(o.y * 0.70710678118654752f));
                }
                if (EPI == 2) {
                    float2 r2 = *(const float2*)(res + (size_t)row * Ncol + col);
                    o.x += r2.x;
                    o.y += r2.y;
                }
                *(float2*)(C + (size_t)row * Ncol + col) = o;
            }
        }
    }
}

// ---------------------------------------------------------------------------
// Fused window attention, one block per (window, head).
// Warp-per-row softmax (8 warps stride rows, lanes stride columns).
// ---------------------------------------------------------------------------
__global__ __launch_bounds__(256)
void attn_kernel(const float* __restrict__ qkv,
                 const float* __restrict__ bias_table,
                 float* __restrict__ out) {
    int w = blockIdx.x;
    int h = blockIdx.y;
    __shared__ float qs[NTOK][HD_ + 1];
    __shared__ float ks[NTOK][HD_ + 1];
    __shared__ float vs[NTOK][HD_ + 1];
    __shared__ float sc[NTOK][NTOK + 1];
    int tid  = threadIdx.x;
    int wid  = tid >> 5;
    int lane = tid & 31;
    const float scale = 0.17677669529663687f;

    for (int i = tid; i < NTOK * HD_; i += 256) {
        int n = i >> 5, d = i & 31;
        size_t base = ((size_t)(w * NTOK + n)) * (3 * C_DIM) + h * HD_ + d;
        qs[n][d] = qkv[base] * scale;
        ks[n][d] = qkv[base + C_DIM];
        vs[n][d] = qkv[base + 2 * C_DIM];
    }
    __syncthreads();

    for (int i = tid; i < NTOK * NTOK; i += 256) {
        int n = i / NTOK, m = i % NTOK;
        float a = 0.f;
        #pragma unroll
        for (int d = 0; d < HD_; d++) a += qs[n][d] * ks[m][d];
        int ni = n / WS_, nj = n % WS_;
        int mi = m / WS_, mj = m % WS_;
        int ridx = (ni - mi + WS_ - 1) * (2 * WS_ - 1) + (nj - mj + WS_ - 1);
        sc[n][m] = a + bias_table[ridx * NH_ + h];
    }
    __syncthreads();

    // warp-per-row softmax
    for (int n = wid; n < NTOK; n += 8) {
        float mx = -1e30f;
        for (int m = lane; m < NTOK; m += 32) mx = fmaxf(mx, sc[n][m]);
        #pragma unroll
        for (int o = 16; o > 0; o >>= 1)
            mx = fmaxf(mx, __shfl_xor_sync(0xffffffffu, mx, o));
        float sum = 0.f;
        float e0 = 0.f, e1 = 0.f;
        if (lane < NTOK)      e0 = __expf(sc[n][lane] - mx);
        if (lane + 32 < NTOK) e1 = __expf(sc[n][lane + 32] - mx);
        sum = e0 + e1;
        #pragma unroll
        for (int o = 16; o > 0; o >>= 1)
            sum += __shfl_xor_sync(0xffffffffu, sum, o);
        float inv = 1.0f / sum;
        if (lane < NTOK)      sc[n][lane]      = e0 * inv;
        if (lane + 32 < NTOK) sc[n][lane + 32] = e1 * inv;
    }
    __syncthreads();

    for (int i = tid; i < NTOK * HD_; i += 256) {
        int n = i >> 5, d = i & 31;
        float a = 0.f;
        #pragma unroll 7
        for (int m = 0; m < NTOK; m++) a += sc[n][m] * vs[m][d];
        out[((size_t)(w * NTOK + n)) * C_DIM + h * HD_ + d] = a;
    }
}

// ---------------------------------------------------------------------------
extern "C" void kernel_launch(void* const* d_in, const int* in_sizes, int n_in,
                              void* d_out, int out_size) {
    const float* x          = (const float*)d_in[0];
    const float* qkv_w      = (const float*)d_in[1];
    const float* qkv_b      = (const float*)d_in[2];
    const float* proj_w     = (const float*)d_in[3];
    const float* proj_b     = (const float*)d_in[4];
    const float* bias_table = (const float*)d_in[5];
    const float* norm1_g    = (const float*)d_in[6];
    const float* norm1_b    = (const float*)d_in[7];
    const float* norm2_g    = (const float*)d_in[8];
    const float* norm2_b    = (const float*)d_in[9];
    const float* mlp_w1     = (const float*)d_in[10];
    const float* mlp_b1     = (const float*)d_in[11];
    const float* mlp_w2     = (const float*)d_in[12];
    const float* mlp_b2     = (const float*)d_in[13];
    float* out = (float*)d_out;

    float *p_xw, *p_qkv, *p_y, *p_x2, *p_h2, *p_mlp;
    cudaGetSymbolAddress((void**)&p_xw,  g_xw);
    cudaGetSymbolAddress((void**)&p_qkv, g_qkv);
    cudaGetSymbolAddress((void**)&p_y,   g_y);
    cudaGetSymbolAddress((void**)&p_x2,  g_x2);
    cudaGetSymbolAddress((void**)&p_h2,  g_h2);
    cudaGetSymbolAddress((void**)&p_mlp, g_mlp);

    ln1_shift_window_kernel<<<T_TOKENS, C_DIM>>>(x, norm1_g, norm1_b, p_xw);

    {   // QKV: [50176,192] @ [192,576]
        dim3 grid(576 / 64, T_TOKENS / 128);
        gemm_tc_kernel<0><<<grid, 256>>>(p_xw, qkv_w, qkv_b, nullptr, p_qkv,
                                         T_TOKENS, 3 * C_DIM, C_DIM);
    }
    {   // attention
        dim3 grid(NWIN, NH_);
        attn_kernel<<<grid, 256>>>(p_qkv, bias_table, p_xw);
    }
    {   // proj: [50176,192] @ [192,192]
        dim3 grid(192 / 64, T_TOKENS / 128);
        gemm_tc_kernel<0><<<grid, 256>>>(p_xw, proj_w, proj_b, nullptr, p_y,
                                         T_TOKENS, C_DIM, C_DIM);
    }
    scatter_res_ln2_kernel<<<T_TOKENS, C_DIM>>>(x, p_y, norm2_g, norm2_b,
                                                p_x2, p_h2);
    {   // MLP1 + GELU: [50176,192] @ [192,768]
        dim3 grid(768 / 64, T_TOKENS / 128);
        gemm_tc_kernel<1><<<grid, 256>>>(p_h2, mlp_w1, mlp_b1, nullptr, p_mlp,
                                         T_TOKENS, 4 * C_DIM, C_DIM);
    }
    {   // MLP2 + residual: [50176,768] @ [768,192]
        dim3 grid(192 / 64, T_TOKENS / 128);
        gemm_tc_kernel<2><<<grid, 256>>>(p_mlp, mlp_w2, mlp_b2, p_x2, out,
                                         T_TOKENS, C_DIM, 4 * C_DIM);
    }
}